// round 15
// baseline (speedup 1.0000x reference)
#include <cuda_runtime.h>
#include <cuda_bf16.h>
#include <cuda_fp16.h>
#include <cstdint>

#define N_NODES 100000
#define N_EDGES 600000
#define E_TOT   700000      // edges + self loops
#define D       128
#define SCAN_B  1024
#define NB      ((N_NODES + SCAN_B - 1) / SCAN_B)   // 98
#define N_TILES ((N_NODES + 127) / 128)              // 782
#define AGG_BLKS (N_NODES * 32 / 256)                // 12500 exactly

#define XPAD    136                                   // padded row length (bf16 elems)
#define TILE_B  (128 * XPAD * 2)                      // 34816 bytes per bf16 tile
// dynamic smem layout (bytes)
#define SM_XHI  0
#define SM_XLO  (TILE_B)
#define SM_WHI  (2 * TILE_B)
#define SM_WLO  (3 * TILE_B)
#define SM_ALPH (4 * TILE_B)                          // as[128][2], ad[128][2] floats
#define SM_TOT  (4 * TILE_B + 2048)                   // 141312

// ---------------- scratch: __device__ globals only (no allocations) ----------------
__device__ __align__(16) __half g_hh[(size_t)N_NODES * D]; // post-GEMM features (fp16)
__device__ __align__(16) __half g_oh[(size_t)N_NODES * D]; // layer-1 output (fp16)
__device__ __align__(16) unsigned short g_wthi[2][128 * XPAD]; // W^T hi bf16 per layer
__device__ __align__(16) unsigned short g_wtlo[2][128 * XPAD]; // W^T lo bf16 per layer
__device__ float g_as[N_NODES];
__device__ float g_ad[N_NODES];
__device__ float g_ew[E_TOT];         // unnormalized edge weights
__device__ int   g_deg[N_NODES];      // self-zeroing each pass (starts 0)
__device__ int   g_incl[N_NODES];     // inclusive per-block scan
__device__ int   g_bsum[NB];
__device__ int   g_rp[N_NODES + 1];   // CSR row_ptr (by dst)
__device__ int   g_cur[N_NODES];      // scatter cursor (holds exclusive scan first)
__device__ int   g_col[E_TOT];        // src node per incoming edge

// ---------------- mma helper: m16n8k16 row.col f32.bf16.bf16.f32 ----------------
__device__ __forceinline__ void mma_bf16(float* c, uint32_t a0, uint32_t a1, uint32_t a2,
                                         uint32_t a3, uint32_t b0, uint32_t b1) {
    asm volatile(
        "mma.sync.aligned.m16n8k16.row.col.f32.bf16.bf16.f32 "
        "{%0,%1,%2,%3}, {%4,%5,%6,%7}, {%8,%9}, {%0,%1,%2,%3};"
        : "+f"(c[0]), "+f"(c[1]), "+f"(c[2]), "+f"(c[3])
        : "r"(a0), "r"(a1), "r"(a2), "r"(a3), "r"(b0), "r"(b1));
}
__device__ __forceinline__ uint32_t pack_bf16(float x, float y) {
    __nv_bfloat16 bx = __float2bfloat16(x), by = __float2bfloat16(y);
    unsigned short ux = *(unsigned short*)&bx, uy = *(unsigned short*)&by;
    return (uint32_t)ux | ((uint32_t)uy << 16);
}

// ---------------- CSR build (edge_index is int32: [src x E | dst x E]) ------------
__global__ void k_deg_count(const int* __restrict__ ei) {
    int e = blockIdx.x * blockDim.x + threadIdx.x;
    if (e < N_EDGES) {
        int d = ei[N_EDGES + e];
        if ((unsigned)d < N_NODES) atomicAdd(&g_deg[d], 1);
    }
}

// per-block inclusive scan of (deg+1); zeroes g_deg for the next pass
__global__ void __launch_bounds__(SCAN_B) k_scan1() {
    __shared__ int s[SCAN_B];
    int tl = threadIdx.x;
    int t  = blockIdx.x * SCAN_B + tl;
    int v  = 0;
    if (t < N_NODES) {
        v = g_deg[t] + 1;     // +1 self loop
        g_deg[t] = 0;         // self-zero for next replay
    }
    s[tl] = v;
    __syncthreads();
    #pragma unroll
    for (int off = 1; off < SCAN_B; off <<= 1) {
        int add = (tl >= off) ? s[tl - off] : 0;
        __syncthreads();
        s[tl] += add;
        __syncthreads();
    }
    if (t < N_NODES) { g_incl[t] = s[tl]; g_cur[t] = s[tl] - v; }
    if (tl == SCAN_B - 1) g_bsum[blockIdx.x] = s[tl];
}

// folds the 98-entry block-sum prefix into the final scan
__global__ void k_scan23() {
    __shared__ int spre[NB];
    if (threadIdx.x == 0) {
        int run = 0;
        #pragma unroll 2
        for (int i = 0; i < NB; i++) { int b = g_bsum[i]; spre[i] = run; run += b; }
    }
    __syncthreads();
    int t = blockIdx.x * blockDim.x + threadIdx.x;
    if (t < N_NODES) {
        int bp = spre[t >> 10];
        g_rp[t + 1] = g_incl[t] + bp;
        g_cur[t]   += bp;
        if (t == 0) g_rp[0] = 0;
    }
}

__global__ void k_scatter(const int* __restrict__ ei) {
    int e = blockIdx.x * blockDim.x + threadIdx.x;
    if (e >= E_TOT) return;
    int s, d;
    if (e < N_EDGES) { s = ei[e]; d = ei[N_EDGES + e]; }
    else             { s = e - N_EDGES; d = s; }
    if ((unsigned)s >= N_NODES || (unsigned)d >= N_NODES) return;
    int pos = atomicAdd(&g_cur[d], 1);
    g_col[pos] = s;
}

// ---------------- W split+transpose for BOTH layers in one launch -----------------
__global__ void k_wsplit(const float* __restrict__ W1, const float* __restrict__ W2) {
    int t = blockIdx.x * blockDim.x + threadIdx.x;
    if (t >= 2 * D * D) return;
    int layer = t >> 14;           // /(D*D)
    int r = t & (D * D - 1);
    int n = r >> 7, k = r & 127;
    const float* W = layer ? W2 : W1;
    float v = W[k * D + n];
    __nv_bfloat16 hb = __float2bfloat16(v);
    float hf = __bfloat162float(hb);
    __nv_bfloat16 lb = __float2bfloat16(v - hf);
    g_wthi[layer][n * XPAD + k] = *(unsigned short*)&hb;
    g_wtlo[layer][n * XPAD + k] = *(unsigned short*)&lb;
}

// ---------------- HMMA GEMM: H = X*W (split-2 bf16, fp32 accum, fp16 H store) ------
// use_ext=1: X = Xext (fp32).  use_ext=0: X = g_oh (fp16).
__global__ void __launch_bounds__(256) k_gemm(
    const float* __restrict__ Xext, int use_ext, int wl,
    const float* __restrict__ avs, const float* __restrict__ avd)
{
    extern __shared__ unsigned char smem[];
    unsigned short* Xhi = (unsigned short*)(smem + SM_XHI);
    unsigned short* Xlo = (unsigned short*)(smem + SM_XLO);
    unsigned short* Whi = (unsigned short*)(smem + SM_WHI);
    unsigned short* Wlo = (unsigned short*)(smem + SM_WLO);
    float* as_s = (float*)(smem + SM_ALPH);          // [128][2]
    float* ad_s = (float*)(smem + SM_ALPH + 1024);   // [128][2]

    const int tid  = threadIdx.x;
    const int warp = tid >> 5;
    const int lane = tid & 31;
    const int lq   = lane & 3;
    const int lr   = lane >> 2;
    const int row0 = blockIdx.x * 128;
    const int mrow0 = (warp >> 1) * 32;
    const int ncol0 = (warp & 1) * 64;

    {
        const float4* X4 = (const float4*)Xext;
        const uint2*  O2 = (const uint2*)g_oh;
        #pragma unroll
        for (int i = tid; i < 128 * 32; i += 256) {
            int r = i >> 5, c4 = i & 31;
            int gr = row0 + r;
            float4 v;
            if (gr >= N_NODES) {
                v = make_float4(0.f, 0.f, 0.f, 0.f);
            } else if (use_ext) {
                v = X4[(size_t)gr * 32 + c4];
            } else {
                uint2 raw = O2[(size_t)gr * 32 + c4];
                float2 f01 = __half22float2(*(__half2*)&raw.x);
                float2 f23 = __half22float2(*(__half2*)&raw.y);
                v = make_float4(f01.x, f01.y, f23.x, f23.y);
            }
            __nv_bfloat16 h0 = __float2bfloat16(v.x), h1 = __float2bfloat16(v.y);
            __nv_bfloat16 h2 = __float2bfloat16(v.z), h3 = __float2bfloat16(v.w);
            float f0 = __bfloat162float(h0), f1 = __bfloat162float(h1);
            float f2 = __bfloat162float(h2), f3 = __bfloat162float(h3);
            uint2 hw, lw;
            {
                unsigned short u0 = *(unsigned short*)&h0, u1 = *(unsigned short*)&h1;
                unsigned short u2 = *(unsigned short*)&h2, u3 = *(unsigned short*)&h3;
                hw.x = (uint32_t)u0 | ((uint32_t)u1 << 16);
                hw.y = (uint32_t)u2 | ((uint32_t)u3 << 16);
            }
            lw.x = pack_bf16(v.x - f0, v.y - f1);
            lw.y = pack_bf16(v.z - f2, v.w - f3);
            int off = r * XPAD + c4 * 4;
            *(uint2*)&Xhi[off] = hw;
            *(uint2*)&Xlo[off] = lw;
        }
    }
    {
        const uint4* wh = (const uint4*)g_wthi[wl];
        const uint4* wl4 = (const uint4*)g_wtlo[wl];
        uint4* sh = (uint4*)Whi;
        uint4* sl = (uint4*)Wlo;
        #pragma unroll
        for (int i = tid; i < TILE_B / 16; i += 256) { sh[i] = wh[i]; sl[i] = wl4[i]; }
    }
    __syncthreads();

    float acc[2][8][4];
    #pragma unroll
    for (int mt = 0; mt < 2; mt++)
        #pragma unroll
        for (int nt = 0; nt < 8; nt++)
            #pragma unroll
            for (int j = 0; j < 4; j++) acc[mt][nt][j] = 0.f;

    #pragma unroll
    for (int ks = 0; ks < 8; ks++) {
        const int kc = ks * 16 + lq * 2;
        uint32_t bh0[8], bh1[8], bl0[8], bl1[8];
        #pragma unroll
        for (int nt = 0; nt < 8; nt++) {
            int n = ncol0 + nt * 8 + lr;
            bh0[nt] = *(const uint32_t*)&Whi[n * XPAD + kc];
            bh1[nt] = *(const uint32_t*)&Whi[n * XPAD + kc + 8];
            bl0[nt] = *(const uint32_t*)&Wlo[n * XPAD + kc];
            bl1[nt] = *(const uint32_t*)&Wlo[n * XPAD + kc + 8];
        }
        #pragma unroll
        for (int mt = 0; mt < 2; mt++) {
            int r0 = mrow0 + mt * 16 + lr;
            uint32_t ah0 = *(const uint32_t*)&Xhi[r0 * XPAD + kc];
            uint32_t ah1 = *(const uint32_t*)&Xhi[(r0 + 8) * XPAD + kc];
            uint32_t ah2 = *(const uint32_t*)&Xhi[r0 * XPAD + kc + 8];
            uint32_t ah3 = *(const uint32_t*)&Xhi[(r0 + 8) * XPAD + kc + 8];
            uint32_t al0 = *(const uint32_t*)&Xlo[r0 * XPAD + kc];
            uint32_t al1 = *(const uint32_t*)&Xlo[(r0 + 8) * XPAD + kc];
            uint32_t al2 = *(const uint32_t*)&Xlo[r0 * XPAD + kc + 8];
            uint32_t al3 = *(const uint32_t*)&Xlo[(r0 + 8) * XPAD + kc + 8];
            #pragma unroll
            for (int nt = 0; nt < 8; nt++) {
                mma_bf16(acc[mt][nt], ah0, ah1, ah2, ah3, bh0[nt], bh1[nt]);
                mma_bf16(acc[mt][nt], ah0, ah1, ah2, ah3, bl0[nt], bl1[nt]);
                mma_bf16(acc[mt][nt], al0, al1, al2, al3, bh0[nt], bh1[nt]);
            }
        }
    }

    #pragma unroll
    for (int mt = 0; mt < 2; mt++) {
        int rl0 = mrow0 + mt * 16 + lr;
        int gr0 = row0 + rl0, gr1 = gr0 + 8;
        float ps0 = 0.f, ps1 = 0.f, pd0 = 0.f, pd1 = 0.f;
        #pragma unroll
        for (int nt = 0; nt < 8; nt++) {
            int c = ncol0 + nt * 8 + lq * 2;
            float s0 = avs[c], s1 = avs[c + 1];
            float d0 = avd[c], d1 = avd[c + 1];
            float* a = acc[mt][nt];
            ps0 += a[0] * s0 + a[1] * s1;
            pd0 += a[0] * d0 + a[1] * d1;
            ps1 += a[2] * s0 + a[3] * s1;
            pd1 += a[2] * d0 + a[3] * d1;
            if (gr0 < N_NODES)
                *(__half2*)&g_hh[(size_t)gr0 * D + c] = __floats2half2_rn(a[0], a[1]);
            if (gr1 < N_NODES)
                *(__half2*)&g_hh[(size_t)gr1 * D + c] = __floats2half2_rn(a[2], a[3]);
        }
        #pragma unroll
        for (int off = 1; off < 4; off <<= 1) {
            ps0 += __shfl_xor_sync(0xffffffffu, ps0, off);
            ps1 += __shfl_xor_sync(0xffffffffu, ps1, off);
            pd0 += __shfl_xor_sync(0xffffffffu, pd0, off);
            pd1 += __shfl_xor_sync(0xffffffffu, pd1, off);
        }
        if (lq == 0) {
            int half = warp & 1;
            as_s[rl0 * 2 + half] = ps0;       as_s[(rl0 + 8) * 2 + half] = ps1;
            ad_s[rl0 * 2 + half] = pd0;       ad_s[(rl0 + 8) * 2 + half] = pd1;
        }
    }
    __syncthreads();
    if (tid < 128) {
        int gr = row0 + tid;
        if (gr < N_NODES) {
            g_as[gr] = as_s[tid * 2] + as_s[tid * 2 + 1];
            g_ad[gr] = ad_s[tid * 2] + ad_s[tid * 2 + 1];
        }
    }
}

// ---------------- warp-per-node 2-pass softmax-aggregate (max-free, exact) --------
// mode 0: layer 1 -> relu, write g_oh (fp16).
// mode 1: layer 2 -> block partial, scaled by 1/N, atomicAdd into out.
__global__ void __launch_bounds__(256) k_node_agg(int mode, const float* __restrict__ b,
                                                  float* __restrict__ out)
{
    __shared__ float sb[8 * 128];
    int node = (blockIdx.x * blockDim.x + threadIdx.x) >> 5;
    int warp = threadIdx.x >> 5;
    int lane = threadIdx.x & 31;

    int beg = g_rp[node];
    int end = g_rp[node + 1];
    float ad = g_ad[node];

    // pass A: unnormalized weights -> g_ew, accumulate denominator
    float wsum = 0.f;
    for (int j = beg + lane; j < end; j += 32) {
        float e = g_as[g_col[j]] + ad;
        e = fmaxf(e, 0.f) + 0.2f * fminf(e, 0.f);
        float w = __expf(e);
        g_ew[j] = w;
        wsum += w;
    }
    #pragma unroll
    for (int off = 16; off; off >>= 1)
        wsum += __shfl_xor_sync(0xffffffffu, wsum, off);
    float inv = 1.f / wsum;
    __syncwarp();

    // pass B: feature accumulate (lane owns 4 columns, fp16 gather = 8B/lane)
    float4 acc = make_float4(0.f, 0.f, 0.f, 0.f);
    for (int j = beg; j < end; j++) {
        int   s = g_col[j];     // warp-uniform broadcast
        float w = g_ew[j];      // warp-uniform broadcast
        uint2 raw = *(const uint2*)&g_hh[(size_t)s * D + lane * 4];
        float2 f01 = __half22float2(*(__half2*)&raw.x);
        float2 f23 = __half22float2(*(__half2*)&raw.y);
        acc.x = fmaf(w, f01.x, acc.x);
        acc.y = fmaf(w, f01.y, acc.y);
        acc.z = fmaf(w, f23.x, acc.z);
        acc.w = fmaf(w, f23.y, acc.w);
    }

    const float4 b4 = *(const float4*)&b[lane * 4];
    acc.x = fmaf(acc.x, inv, b4.x);
    acc.y = fmaf(acc.y, inv, b4.y);
    acc.z = fmaf(acc.z, inv, b4.z);
    acc.w = fmaf(acc.w, inv, b4.w);

    if (mode == 0) {
        acc.x = fmaxf(acc.x, 0.f); acc.y = fmaxf(acc.y, 0.f);
        acc.z = fmaxf(acc.z, 0.f); acc.w = fmaxf(acc.w, 0.f);
        uint2 st;
        *(__half2*)&st.x = __floats2half2_rn(acc.x, acc.y);
        *(__half2*)&st.y = __floats2half2_rn(acc.z, acc.w);
        *(uint2*)&g_oh[(size_t)node * D + lane * 4] = st;
    } else {
        // layer 2: block partial sum, scaled by 1/N, accumulated into d_out
        *(float4*)&sb[warp * 128 + lane * 4] = acc;
        __syncthreads();
        if (threadIdx.x < 128) {
            float s = 0.f;
            #pragma unroll
            for (int w = 0; w < 8; w++) s += sb[w * 128 + threadIdx.x];
            atomicAdd(&out[threadIdx.x], s * (1.0f / N_NODES));
        }
    }
}

// ---------------- zero d_out (poisoned 0xAA by harness) ---------------------------
__global__ void k_zero_out(float* __restrict__ out) {
    if (threadIdx.x < 128) out[threadIdx.x] = 0.f;
}

// ---------------- driver: fork CSR build onto a side stream, join before agg1 -----
extern "C" void kernel_launch(void* const* d_in, const int* in_sizes, int n_in,
                              void* d_out, int out_size)
{
    const float* x   = (const float*)d_in[0];
    const int*   ei  = (const int*)d_in[1];      // int32: [src x E | dst x E]
    const float* W1  = (const float*)d_in[2];
    const float* as1 = (const float*)d_in[3];
    const float* ad1 = (const float*)d_in[4];
    const float* b1  = (const float*)d_in[5];
    const float* W2  = (const float*)d_in[6];
    const float* as2 = (const float*)d_in[7];
    const float* ad2 = (const float*)d_in[8];
    const float* b2  = (const float*)d_in[9];
    float* out = (float*)d_out;

    // one-time host-object setup (first call is the uncaptured correctness run;
    // no device memory is allocated here)
    static cudaStream_t s2 = nullptr;
    static cudaEvent_t ev_fork = nullptr, ev_csr = nullptr;
    if (s2 == nullptr) {
        cudaStreamCreateWithFlags(&s2, cudaStreamNonBlocking);
        cudaEventCreateWithFlags(&ev_fork, cudaEventDisableTiming);
        cudaEventCreateWithFlags(&ev_csr,  cudaEventDisableTiming);
        cudaFuncSetAttribute(k_gemm, cudaFuncAttributeMaxDynamicSharedMemorySize, SM_TOT);
    }

    // fork: side stream builds CSR while main stream does wsplit + layer-1 GEMM
    cudaEventRecord(ev_fork, 0);
    cudaStreamWaitEvent(s2, ev_fork, 0);

    k_deg_count<<<(N_EDGES + 255) / 256, 256, 0, s2>>>(ei);
    k_scan1    <<<NB, SCAN_B, 0, s2>>>();
    k_scan23   <<<(N_NODES + 255) / 256, 256, 0, s2>>>();
    k_scatter  <<<(E_TOT + 255) / 256, 256, 0, s2>>>(ei);
    cudaEventRecord(ev_csr, s2);

    k_zero_out<<<1, 128>>>(out);
    k_wsplit<<<(2 * D * D + 255) / 256, 256>>>(W1, W2);
    k_gemm  <<<N_TILES, 256, SM_TOT>>>(x, 1, 0, as1, ad1);

    // join: aggregation needs both the CSR and layer-1 H/alphas
    cudaStreamWaitEvent(0, ev_csr, 0);

    // layer 1 aggregate -> g_oh (relu, fp16)
    k_node_agg<<<AGG_BLKS, 256>>>(0, b1, out);

    // layer 2: g_oh -> g_hh -> scaled partials atomically accumulated into d_out
    k_gemm    <<<N_TILES, 256, SM_TOT>>>(nullptr, 0, 1, as2, ad2);
    k_node_agg<<<AGG_BLKS, 256>>>(1, b2, out);
}

// round 16
// speedup vs baseline: 1.0121x; 1.0121x over previous
#include <cuda_runtime.h>
#include <cuda_bf16.h>
#include <cuda_fp16.h>
#include <cstdint>

#define N_NODES 100000
#define N_EDGES 600000
#define E_TOT   700000      // edges + self loops
#define D       128
#define SCAN_B  1024
#define NB      ((N_NODES + SCAN_B - 1) / SCAN_B)   // 98
#define N_TILES ((N_NODES + 127) / 128)              // 782
#define AGG_BLKS (N_NODES * 32 / 256)                // 12500 exactly

#define XPAD    136                                   // padded row length (bf16 elems)
#define TILE_B  (128 * XPAD * 2)                      // 34816 bytes per bf16 tile
// dynamic smem layout (bytes)
#define SM_XHI  0
#define SM_XLO  (TILE_B)
#define SM_WHI  (2 * TILE_B)
#define SM_WLO  (3 * TILE_B)
#define SM_ALPH (4 * TILE_B)                          // as[128][2], ad[128][2] floats
#define SM_TOT  (4 * TILE_B + 2048)                   // 141312

// ---------------- scratch: __device__ globals only (no allocations) ----------------
__device__ __align__(16) __half g_hh[(size_t)N_NODES * D]; // post-GEMM features (fp16)
__device__ __align__(16) float g_o[(size_t)N_NODES * D];   // layer-1 output (fp32)
__device__ __align__(16) unsigned short g_wthi[2][128 * XPAD]; // W^T hi bf16 per layer
__device__ __align__(16) unsigned short g_wtlo[2][128 * XPAD]; // W^T lo bf16 per layer
__device__ float g_as[N_NODES];
__device__ float g_ad[N_NODES];
__device__ int   g_deg[N_NODES];      // self-zeroing each pass (starts 0)
__device__ int   g_incl[N_NODES];     // inclusive per-block scan
__device__ int   g_bsum[NB];
__device__ int   g_rp[N_NODES + 1];   // CSR row_ptr (by dst)
__device__ int   g_cur[N_NODES];      // scatter cursor (holds exclusive scan first)
__device__ int   g_col[E_TOT];        // src node per incoming edge

// ---------------- mma helper: m16n8k16 row.col f32.bf16.bf16.f32 ----------------
__device__ __forceinline__ void mma_bf16(float* c, uint32_t a0, uint32_t a1, uint32_t a2,
                                         uint32_t a3, uint32_t b0, uint32_t b1) {
    asm volatile(
        "mma.sync.aligned.m16n8k16.row.col.f32.bf16.bf16.f32 "
        "{%0,%1,%2,%3}, {%4,%5,%6,%7}, {%8,%9}, {%0,%1,%2,%3};"
        : "+f"(c[0]), "+f"(c[1]), "+f"(c[2]), "+f"(c[3])
        : "r"(a0), "r"(a1), "r"(a2), "r"(a3), "r"(b0), "r"(b1));
}
__device__ __forceinline__ uint32_t pack_bf16(float x, float y) {
    __nv_bfloat16 bx = __float2bfloat16(x), by = __float2bfloat16(y);
    unsigned short ux = *(unsigned short*)&bx, uy = *(unsigned short*)&by;
    return (uint32_t)ux | ((uint32_t)uy << 16);
}

// ---------------- CSR build (edge_index is int32: [src x E | dst x E]) ------------
__global__ void k_deg_count(const int* __restrict__ ei) {
    int e = blockIdx.x * blockDim.x + threadIdx.x;
    if (e < N_EDGES) {
        int d = ei[N_EDGES + e];
        if ((unsigned)d < N_NODES) atomicAdd(&g_deg[d], 1);
    }
}

// per-block inclusive scan of (deg+1); zeroes g_deg for the next pass
__global__ void __launch_bounds__(SCAN_B) k_scan1() {
    __shared__ int s[SCAN_B];
    int tl = threadIdx.x;
    int t  = blockIdx.x * SCAN_B + tl;
    int v  = 0;
    if (t < N_NODES) {
        v = g_deg[t] + 1;     // +1 self loop
        g_deg[t] = 0;         // self-zero for next replay
    }
    s[tl] = v;
    __syncthreads();
    #pragma unroll
    for (int off = 1; off < SCAN_B; off <<= 1) {
        int add = (tl >= off) ? s[tl - off] : 0;
        __syncthreads();
        s[tl] += add;
        __syncthreads();
    }
    if (t < N_NODES) { g_incl[t] = s[tl]; g_cur[t] = s[tl] - v; }
    if (tl == SCAN_B - 1) g_bsum[blockIdx.x] = s[tl];
}

// folds the 98-entry block-sum prefix into the final scan
__global__ void k_scan23() {
    __shared__ int spre[NB];
    if (threadIdx.x == 0) {
        int run = 0;
        #pragma unroll 2
        for (int i = 0; i < NB; i++) { int b = g_bsum[i]; spre[i] = run; run += b; }
    }
    __syncthreads();
    int t = blockIdx.x * blockDim.x + threadIdx.x;
    if (t < N_NODES) {
        int bp = spre[t >> 10];
        g_rp[t + 1] = g_incl[t] + bp;
        g_cur[t]   += bp;
        if (t == 0) g_rp[0] = 0;
    }
}

__global__ void k_scatter(const int* __restrict__ ei) {
    int e = blockIdx.x * blockDim.x + threadIdx.x;
    if (e >= E_TOT) return;
    int s, d;
    if (e < N_EDGES) { s = ei[e]; d = ei[N_EDGES + e]; }
    else             { s = e - N_EDGES; d = s; }
    if ((unsigned)s >= N_NODES || (unsigned)d >= N_NODES) return;
    int pos = atomicAdd(&g_cur[d], 1);
    g_col[pos] = s;
}

// ---------------- W split+transpose for BOTH layers in one launch -----------------
__global__ void k_wsplit(const float* __restrict__ W1, const float* __restrict__ W2) {
    int t = blockIdx.x * blockDim.x + threadIdx.x;
    if (t >= 2 * D * D) return;
    int layer = t >> 14;           // /(D*D)
    int r = t & (D * D - 1);
    int n = r >> 7, k = r & 127;
    const float* W = layer ? W2 : W1;
    float v = W[k * D + n];
    __nv_bfloat16 hb = __float2bfloat16(v);
    float hf = __bfloat162float(hb);
    __nv_bfloat16 lb = __float2bfloat16(v - hf);
    g_wthi[layer][n * XPAD + k] = *(unsigned short*)&hb;
    g_wtlo[layer][n * XPAD + k] = *(unsigned short*)&lb;
}

// ---------------- HMMA GEMM: H = X*W (split-2 bf16, fp32 accum, fp16 H store) ------
__global__ void __launch_bounds__(256) k_gemm(
    const float* __restrict__ Xext, int use_ext, int wl,
    const float* __restrict__ avs, const float* __restrict__ avd)
{
    extern __shared__ unsigned char smem[];
    unsigned short* Xhi = (unsigned short*)(smem + SM_XHI);
    unsigned short* Xlo = (unsigned short*)(smem + SM_XLO);
    unsigned short* Whi = (unsigned short*)(smem + SM_WHI);
    unsigned short* Wlo = (unsigned short*)(smem + SM_WLO);
    float* as_s = (float*)(smem + SM_ALPH);          // [128][2]
    float* ad_s = (float*)(smem + SM_ALPH + 1024);   // [128][2]

    const int tid  = threadIdx.x;
    const int warp = tid >> 5;
    const int lane = tid & 31;
    const int lq   = lane & 3;
    const int lr   = lane >> 2;
    const int row0 = blockIdx.x * 128;
    const int mrow0 = (warp >> 1) * 32;
    const int ncol0 = (warp & 1) * 64;
    const float* X = use_ext ? Xext : g_o;

    {
        const float4* X4 = (const float4*)X;
        #pragma unroll
        for (int i = tid; i < 128 * 32; i += 256) {
            int r = i >> 5, c4 = i & 31;
            int gr = row0 + r;
            float4 v = (gr < N_NODES) ? X4[(size_t)gr * 32 + c4]
                                      : make_float4(0.f, 0.f, 0.f, 0.f);
            __nv_bfloat16 h0 = __float2bfloat16(v.x), h1 = __float2bfloat16(v.y);
            __nv_bfloat16 h2 = __float2bfloat16(v.z), h3 = __float2bfloat16(v.w);
            float f0 = __bfloat162float(h0), f1 = __bfloat162float(h1);
            float f2 = __bfloat162float(h2), f3 = __bfloat162float(h3);
            uint2 hw, lw;
            {
                unsigned short u0 = *(unsigned short*)&h0, u1 = *(unsigned short*)&h1;
                unsigned short u2 = *(unsigned short*)&h2, u3 = *(unsigned short*)&h3;
                hw.x = (uint32_t)u0 | ((uint32_t)u1 << 16);
                hw.y = (uint32_t)u2 | ((uint32_t)u3 << 16);
            }
            lw.x = pack_bf16(v.x - f0, v.y - f1);
            lw.y = pack_bf16(v.z - f2, v.w - f3);
            int off = r * XPAD + c4 * 4;
            *(uint2*)&Xhi[off] = hw;
            *(uint2*)&Xlo[off] = lw;
        }
    }
    {
        const uint4* wh = (const uint4*)g_wthi[wl];
        const uint4* wl4 = (const uint4*)g_wtlo[wl];
        uint4* sh = (uint4*)Whi;
        uint4* sl = (uint4*)Wlo;
        #pragma unroll
        for (int i = tid; i < TILE_B / 16; i += 256) { sh[i] = wh[i]; sl[i] = wl4[i]; }
    }
    __syncthreads();

    float acc[2][8][4];
    #pragma unroll
    for (int mt = 0; mt < 2; mt++)
        #pragma unroll
        for (int nt = 0; nt < 8; nt++)
            #pragma unroll
            for (int j = 0; j < 4; j++) acc[mt][nt][j] = 0.f;

    #pragma unroll
    for (int ks = 0; ks < 8; ks++) {
        const int kc = ks * 16 + lq * 2;
        uint32_t bh0[8], bh1[8], bl0[8], bl1[8];
        #pragma unroll
        for (int nt = 0; nt < 8; nt++) {
            int n = ncol0 + nt * 8 + lr;
            bh0[nt] = *(const uint32_t*)&Whi[n * XPAD + kc];
            bh1[nt] = *(const uint32_t*)&Whi[n * XPAD + kc + 8];
            bl0[nt] = *(const uint32_t*)&Wlo[n * XPAD + kc];
            bl1[nt] = *(const uint32_t*)&Wlo[n * XPAD + kc + 8];
        }
        #pragma unroll
        for (int mt = 0; mt < 2; mt++) {
            int r0 = mrow0 + mt * 16 + lr;
            uint32_t ah0 = *(const uint32_t*)&Xhi[r0 * XPAD + kc];
            uint32_t ah1 = *(const uint32_t*)&Xhi[(r0 + 8) * XPAD + kc];
            uint32_t ah2 = *(const uint32_t*)&Xhi[r0 * XPAD + kc + 8];
            uint32_t ah3 = *(const uint32_t*)&Xhi[(r0 + 8) * XPAD + kc + 8];
            uint32_t al0 = *(const uint32_t*)&Xlo[r0 * XPAD + kc];
            uint32_t al1 = *(const uint32_t*)&Xlo[(r0 + 8) * XPAD + kc];
            uint32_t al2 = *(const uint32_t*)&Xlo[r0 * XPAD + kc + 8];
            uint32_t al3 = *(const uint32_t*)&Xlo[(r0 + 8) * XPAD + kc + 8];
            #pragma unroll
            for (int nt = 0; nt < 8; nt++) {
                mma_bf16(acc[mt][nt], ah0, ah1, ah2, ah3, bh0[nt], bh1[nt]);
                mma_bf16(acc[mt][nt], ah0, ah1, ah2, ah3, bl0[nt], bl1[nt]);
                mma_bf16(acc[mt][nt], al0, al1, al2, al3, bh0[nt], bh1[nt]);
            }
        }
    }

    #pragma unroll
    for (int mt = 0; mt < 2; mt++) {
        int rl0 = mrow0 + mt * 16 + lr;
        int gr0 = row0 + rl0, gr1 = gr0 + 8;
        float ps0 = 0.f, ps1 = 0.f, pd0 = 0.f, pd1 = 0.f;
        #pragma unroll
        for (int nt = 0; nt < 8; nt++) {
            int c = ncol0 + nt * 8 + lq * 2;
            float s0 = avs[c], s1 = avs[c + 1];
            float d0 = avd[c], d1 = avd[c + 1];
            float* a = acc[mt][nt];
            ps0 += a[0] * s0 + a[1] * s1;
            pd0 += a[0] * d0 + a[1] * d1;
            ps1 += a[2] * s0 + a[3] * s1;
            pd1 += a[2] * d0 + a[3] * d1;
            if (gr0 < N_NODES)
                *(__half2*)&g_hh[(size_t)gr0 * D + c] = __floats2half2_rn(a[0], a[1]);
            if (gr1 < N_NODES)
                *(__half2*)&g_hh[(size_t)gr1 * D + c] = __floats2half2_rn(a[2], a[3]);
        }
        #pragma unroll
        for (int off = 1; off < 4; off <<= 1) {
            ps0 += __shfl_xor_sync(0xffffffffu, ps0, off);
            ps1 += __shfl_xor_sync(0xffffffffu, ps1, off);
            pd0 += __shfl_xor_sync(0xffffffffu, pd0, off);
            pd1 += __shfl_xor_sync(0xffffffffu, pd1, off);
        }
        if (lq == 0) {
            int half = warp & 1;
            as_s[rl0 * 2 + half] = ps0;       as_s[(rl0 + 8) * 2 + half] = ps1;
            ad_s[rl0 * 2 + half] = pd0;       ad_s[(rl0 + 8) * 2 + half] = pd1;
        }
    }
    __syncthreads();
    if (tid < 128) {
        int gr = row0 + tid;
        if (gr < N_NODES) {
            g_as[gr] = as_s[tid * 2] + as_s[tid * 2 + 1];
            g_ad[gr] = ad_s[tid * 2] + ad_s[tid * 2 + 1];
        }
    }
}

// ---------------- warp-per-node 2-pass softmax-aggregate (max-free, exact) --------
// mode 0: layer 1 -> relu, write g_o (fp32).
// mode 1: layer 2 -> block partial, scaled by 1/N, atomicAdd into out.
// No g_ew buffer: pass B recomputes w from g_as (bit-identical inputs/ops).
__device__ __forceinline__ float edge_w(int col, float ad) {
    float e = g_as[col] + ad;
    e = fmaxf(e, 0.f) + 0.2f * fminf(e, 0.f);
    return __expf(e);
}

__global__ void __launch_bounds__(256) k_node_agg(int mode, const float* __restrict__ b,
                                                  float* __restrict__ out)
{
    __shared__ float sb[8 * 128];
    int node = (blockIdx.x * blockDim.x + threadIdx.x) >> 5;
    int warp = threadIdx.x >> 5;
    int lane = threadIdx.x & 31;

    int beg = g_rp[node];
    int end = g_rp[node + 1];
    float ad = g_ad[node];

    // pass A: denominator only (lane-parallel scattered g_as loads)
    float wsum = 0.f;
    for (int j = beg + lane; j < end; j += 32)
        wsum += edge_w(g_col[j], ad);
    #pragma unroll
    for (int off = 16; off; off >>= 1)
        wsum += __shfl_xor_sync(0xffffffffu, wsum, off);
    float inv = 1.f / wsum;

    // pass B: feature accumulate (w recomputed from broadcast g_as load)
    float4 acc = make_float4(0.f, 0.f, 0.f, 0.f);
    for (int j = beg; j < end; j++) {
        int   s = g_col[j];          // warp-uniform broadcast
        float w = edge_w(s, ad);     // warp-uniform (g_as L2-hot from pass A)
        uint2 raw = *(const uint2*)&g_hh[(size_t)s * D + lane * 4];
        float2 f01 = __half22float2(*(__half2*)&raw.x);
        float2 f23 = __half22float2(*(__half2*)&raw.y);
        acc.x = fmaf(w, f01.x, acc.x);
        acc.y = fmaf(w, f01.y, acc.y);
        acc.z = fmaf(w, f23.x, acc.z);
        acc.w = fmaf(w, f23.y, acc.w);
    }

    const float4 b4 = *(const float4*)&b[lane * 4];
    acc.x = fmaf(acc.x, inv, b4.x);
    acc.y = fmaf(acc.y, inv, b4.y);
    acc.z = fmaf(acc.z, inv, b4.z);
    acc.w = fmaf(acc.w, inv, b4.w);

    if (mode == 0) {
        acc.x = fmaxf(acc.x, 0.f); acc.y = fmaxf(acc.y, 0.f);
        acc.z = fmaxf(acc.z, 0.f); acc.w = fmaxf(acc.w, 0.f);
        *(float4*)&g_o[(size_t)node * D + lane * 4] = acc;
    } else {
        // layer 2: block partial sum, scaled by 1/N, accumulated into d_out
        *(float4*)&sb[warp * 128 + lane * 4] = acc;
        __syncthreads();
        if (threadIdx.x < 128) {
            float s = 0.f;
            #pragma unroll
            for (int w = 0; w < 8; w++) s += sb[w * 128 + threadIdx.x];
            atomicAdd(&out[threadIdx.x], s * (1.0f / N_NODES));
        }
    }
}

// ---------------- zero d_out (poisoned 0xAA by harness) ---------------------------
__global__ void k_zero_out(float* __restrict__ out) {
    if (threadIdx.x < 128) out[threadIdx.x] = 0.f;
}

// ---------------- driver: fork CSR build onto a side stream, join before agg1 -----
extern "C" void kernel_launch(void* const* d_in, const int* in_sizes, int n_in,
                              void* d_out, int out_size)
{
    const float* x   = (const float*)d_in[0];
    const int*   ei  = (const int*)d_in[1];      // int32: [src x E | dst x E]
    const float* W1  = (const float*)d_in[2];
    const float* as1 = (const float*)d_in[3];
    const float* ad1 = (const float*)d_in[4];
    const float* b1  = (const float*)d_in[5];
    const float* W2  = (const float*)d_in[6];
    const float* as2 = (const float*)d_in[7];
    const float* ad2 = (const float*)d_in[8];
    const float* b2  = (const float*)d_in[9];
    float* out = (float*)d_out;

    // one-time host-object setup (first call is the uncaptured correctness run;
    // no device memory is allocated here)
    static cudaStream_t s2 = nullptr;
    static cudaEvent_t ev_fork = nullptr, ev_csr = nullptr;
    if (s2 == nullptr) {
        cudaStreamCreateWithFlags(&s2, cudaStreamNonBlocking);
        cudaEventCreateWithFlags(&ev_fork, cudaEventDisableTiming);
        cudaEventCreateWithFlags(&ev_csr,  cudaEventDisableTiming);
        cudaFuncSetAttribute(k_gemm, cudaFuncAttributeMaxDynamicSharedMemorySize, SM_TOT);
    }

    // fork: side stream zeroes d_out + builds CSR while main stream does
    // wsplit + layer-1 GEMM
    cudaEventRecord(ev_fork, 0);
    cudaStreamWaitEvent(s2, ev_fork, 0);

    k_zero_out <<<1, 128, 0, s2>>>(out);
    k_deg_count<<<(N_EDGES + 255) / 256, 256, 0, s2>>>(ei);
    k_scan1    <<<NB, SCAN_B, 0, s2>>>();
    k_scan23   <<<(N_NODES + 255) / 256, 256, 0, s2>>>();
    k_scatter  <<<(E_TOT + 255) / 256, 256, 0, s2>>>(ei);
    cudaEventRecord(ev_csr, s2);

    k_wsplit<<<(2 * D * D + 255) / 256, 256>>>(W1, W2);
    k_gemm  <<<N_TILES, 256, SM_TOT>>>(x, 1, 0, as1, ad1);

    // join: aggregation needs the CSR, layer-1 H/alphas, and zeroed d_out
    cudaStreamWaitEvent(0, ev_csr, 0);

    // layer 1 aggregate -> g_o (relu, fp32)
    k_node_agg<<<AGG_BLKS, 256>>>(0, b1, out);

    // layer 2: g_o -> g_hh -> scaled partials atomically accumulated into d_out
    k_gemm    <<<N_TILES, 256, SM_TOT>>>(nullptr, 0, 1, as2, ad2);
    k_node_agg<<<AGG_BLKS, 256>>>(1, b2, out);
}

// round 17
// speedup vs baseline: 1.0422x; 1.0298x over previous
#include <cuda_runtime.h>
#include <cuda_bf16.h>
#include <cuda_fp16.h>
#include <cstdint>

#define N_NODES 100000
#define N_EDGES 600000
#define E_TOT   700000      // edges + self loops
#define D       128
#define SCAN_B  1024
#define NB      ((N_NODES + SCAN_B - 1) / SCAN_B)   // 98
#define N_TILES ((N_NODES + 127) / 128)              // 782
#define AGG_BLKS (N_NODES * 32 / 256)                // 12500 exactly

#define XPAD    136                                   // padded row length (bf16 elems)
#define TILE_B  (128 * XPAD * 2)                      // 34816 bytes per bf16 tile
// dynamic smem layout (bytes)
#define SM_XHI  0
#define SM_XLO  (TILE_B)
#define SM_WHI  (2 * TILE_B)
#define SM_WLO  (3 * TILE_B)
#define SM_ALPH (4 * TILE_B)                          // as[128][2], ad[128][2] floats
#define SM_TOT  (4 * TILE_B + 2048)                   // 141312

// ---------------- scratch: __device__ globals only (no allocations) ----------------
__device__ __align__(16) __half g_hh[(size_t)N_NODES * D]; // post-GEMM features (fp16)
__device__ __align__(16) float g_o[(size_t)N_NODES * D];   // layer-1 output (fp32)
__device__ __align__(16) unsigned short g_wthi[2][128 * XPAD]; // W^T hi bf16 per layer
__device__ __align__(16) unsigned short g_wtlo[2][128 * XPAD]; // W^T lo bf16 per layer
__device__ float g_as[N_NODES];
__device__ float g_ad[N_NODES];
__device__ float g_ew[E_TOT];         // unnormalized edge weights
__device__ int   g_deg[N_NODES];      // self-zeroing each pass (starts 0)
__device__ int   g_incl[N_NODES];     // inclusive per-block scan
__device__ int   g_bsum[NB];
__device__ int   g_rp[N_NODES + 1];   // CSR row_ptr (by dst)
__device__ int   g_cur[N_NODES];      // scatter cursor (holds exclusive scan first)
__device__ int   g_col[E_TOT];        // src node per incoming edge

// ---------------- mma helper: m16n8k16 row.col f32.bf16.bf16.f32 ----------------
__device__ __forceinline__ void mma_bf16(float* c, uint32_t a0, uint32_t a1, uint32_t a2,
                                         uint32_t a3, uint32_t b0, uint32_t b1) {
    asm volatile(
        "mma.sync.aligned.m16n8k16.row.col.f32.bf16.bf16.f32 "
        "{%0,%1,%2,%3}, {%4,%5,%6,%7}, {%8,%9}, {%0,%1,%2,%3};"
        : "+f"(c[0]), "+f"(c[1]), "+f"(c[2]), "+f"(c[3])
        : "r"(a0), "r"(a1), "r"(a2), "r"(a3), "r"(b0), "r"(b1));
}
__device__ __forceinline__ uint32_t pack_bf16(float x, float y) {
    __nv_bfloat16 bx = __float2bfloat16(x), by = __float2bfloat16(y);
    unsigned short ux = *(unsigned short*)&bx, uy = *(unsigned short*)&by;
    return (uint32_t)ux | ((uint32_t)uy << 16);
}

// ---------------- CSR build (edge_index is int32: [src x E | dst x E]) ------------
__global__ void k_deg_count(const int* __restrict__ ei) {
    int e = blockIdx.x * blockDim.x + threadIdx.x;
    if (e < N_EDGES) {
        int d = ei[N_EDGES + e];
        if ((unsigned)d < N_NODES) atomicAdd(&g_deg[d], 1);
    }
}

// per-block inclusive scan of (deg+1); zeroes g_deg for the next pass
__global__ void __launch_bounds__(SCAN_B) k_scan1() {
    __shared__ int s[SCAN_B];
    int tl = threadIdx.x;
    int t  = blockIdx.x * SCAN_B + tl;
    int v  = 0;
    if (t < N_NODES) {
        v = g_deg[t] + 1;     // +1 self loop
        g_deg[t] = 0;         // self-zero for next replay
    }
    s[tl] = v;
    __syncthreads();
    #pragma unroll
    for (int off = 1; off < SCAN_B; off <<= 1) {
        int add = (tl >= off) ? s[tl - off] : 0;
        __syncthreads();
        s[tl] += add;
        __syncthreads();
    }
    if (t < N_NODES) { g_incl[t] = s[tl]; g_cur[t] = s[tl] - v; }
    if (tl == SCAN_B - 1) g_bsum[blockIdx.x] = s[tl];
}

// parallel Hillis-Steele scan of the 98 block sums (smem), then final fixup
__global__ void k_scan23() {
    __shared__ int sinc[NB];
    __shared__ int sexc[NB];
    int tl = threadIdx.x;
    int v0 = 0;
    if (tl < NB) { v0 = g_bsum[tl]; sinc[tl] = v0; }
    __syncthreads();
    #pragma unroll
    for (int off = 1; off < 128; off <<= 1) {
        int add = (tl < NB && tl >= off) ? sinc[tl - off] : 0;
        __syncthreads();
        if (tl < NB) sinc[tl] += add;
        __syncthreads();
    }
    if (tl < NB) sexc[tl] = sinc[tl] - v0;   // exclusive prefix
    __syncthreads();
    int t = blockIdx.x * blockDim.x + tl;
    if (t < N_NODES) {
        int bp = sexc[t >> 10];
        g_rp[t + 1] = g_incl[t] + bp;
        g_cur[t]   += bp;
        if (t == 0) g_rp[0] = 0;
    }
}

__global__ void k_scatter(const int* __restrict__ ei) {
    int e = blockIdx.x * blockDim.x + threadIdx.x;
    if (e >= E_TOT) return;
    int s, d;
    if (e < N_EDGES) { s = ei[e]; d = ei[N_EDGES + e]; }
    else             { s = e - N_EDGES; d = s; }
    if ((unsigned)s >= N_NODES || (unsigned)d >= N_NODES) return;
    int pos = atomicAdd(&g_cur[d], 1);
    g_col[pos] = s;
}

// ---------------- W split+transpose for BOTH layers in one launch -----------------
__global__ void k_wsplit(const float* __restrict__ W1, const float* __restrict__ W2) {
    int t = blockIdx.x * blockDim.x + threadIdx.x;
    if (t >= 2 * D * D) return;
    int layer = t >> 14;           // /(D*D)
    int r = t & (D * D - 1);
    int n = r >> 7, k = r & 127;
    const float* W = layer ? W2 : W1;
    float v = W[k * D + n];
    __nv_bfloat16 hb = __float2bfloat16(v);
    float hf = __bfloat162float(hb);
    __nv_bfloat16 lb = __float2bfloat16(v - hf);
    g_wthi[layer][n * XPAD + k] = *(unsigned short*)&hb;
    g_wtlo[layer][n * XPAD + k] = *(unsigned short*)&lb;
}

// ---------------- HMMA GEMM: H = X*W (split-2 bf16, fp32 accum, fp16 H store) ------
__global__ void __launch_bounds__(256) k_gemm(
    const float* __restrict__ Xext, int use_ext, int wl,
    const float* __restrict__ avs, const float* __restrict__ avd)
{
    extern __shared__ unsigned char smem[];
    unsigned short* Xhi = (unsigned short*)(smem + SM_XHI);
    unsigned short* Xlo = (unsigned short*)(smem + SM_XLO);
    unsigned short* Whi = (unsigned short*)(smem + SM_WHI);
    unsigned short* Wlo = (unsigned short*)(smem + SM_WLO);
    float* as_s = (float*)(smem + SM_ALPH);          // [128][2]
    float* ad_s = (float*)(smem + SM_ALPH + 1024);   // [128][2]

    const int tid  = threadIdx.x;
    const int warp = tid >> 5;
    const int lane = tid & 31;
    const int lq   = lane & 3;
    const int lr   = lane >> 2;
    const int row0 = blockIdx.x * 128;
    const int mrow0 = (warp >> 1) * 32;
    const int ncol0 = (warp & 1) * 64;
    const float* X = use_ext ? Xext : g_o;

    {
        const float4* X4 = (const float4*)X;
        #pragma unroll
        for (int i = tid; i < 128 * 32; i += 256) {
            int r = i >> 5, c4 = i & 31;
            int gr = row0 + r;
            float4 v = (gr < N_NODES) ? X4[(size_t)gr * 32 + c4]
                                      : make_float4(0.f, 0.f, 0.f, 0.f);
            __nv_bfloat16 h0 = __float2bfloat16(v.x), h1 = __float2bfloat16(v.y);
            __nv_bfloat16 h2 = __float2bfloat16(v.z), h3 = __float2bfloat16(v.w);
            float f0 = __bfloat162float(h0), f1 = __bfloat162float(h1);
            float f2 = __bfloat162float(h2), f3 = __bfloat162float(h3);
            uint2 hw, lw;
            {
                unsigned short u0 = *(unsigned short*)&h0, u1 = *(unsigned short*)&h1;
                unsigned short u2 = *(unsigned short*)&h2, u3 = *(unsigned short*)&h3;
                hw.x = (uint32_t)u0 | ((uint32_t)u1 << 16);
                hw.y = (uint32_t)u2 | ((uint32_t)u3 << 16);
            }
            lw.x = pack_bf16(v.x - f0, v.y - f1);
            lw.y = pack_bf16(v.z - f2, v.w - f3);
            int off = r * XPAD + c4 * 4;
            *(uint2*)&Xhi[off] = hw;
            *(uint2*)&Xlo[off] = lw;
        }
    }
    {
        const uint4* wh = (const uint4*)g_wthi[wl];
        const uint4* wl4 = (const uint4*)g_wtlo[wl];
        uint4* sh = (uint4*)Whi;
        uint4* sl = (uint4*)Wlo;
        #pragma unroll
        for (int i = tid; i < TILE_B / 16; i += 256) { sh[i] = wh[i]; sl[i] = wl4[i]; }
    }
    __syncthreads();

    float acc[2][8][4];
    #pragma unroll
    for (int mt = 0; mt < 2; mt++)
        #pragma unroll
        for (int nt = 0; nt < 8; nt++)
            #pragma unroll
            for (int j = 0; j < 4; j++) acc[mt][nt][j] = 0.f;

    #pragma unroll
    for (int ks = 0; ks < 8; ks++) {
        const int kc = ks * 16 + lq * 2;
        uint32_t bh0[8], bh1[8], bl0[8], bl1[8];
        #pragma unroll
        for (int nt = 0; nt < 8; nt++) {
            int n = ncol0 + nt * 8 + lr;
            bh0[nt] = *(const uint32_t*)&Whi[n * XPAD + kc];
            bh1[nt] = *(const uint32_t*)&Whi[n * XPAD + kc + 8];
            bl0[nt] = *(const uint32_t*)&Wlo[n * XPAD + kc];
            bl1[nt] = *(const uint32_t*)&Wlo[n * XPAD + kc + 8];
        }
        #pragma unroll
        for (int mt = 0; mt < 2; mt++) {
            int r0 = mrow0 + mt * 16 + lr;
            uint32_t ah0 = *(const uint32_t*)&Xhi[r0 * XPAD + kc];
            uint32_t ah1 = *(const uint32_t*)&Xhi[(r0 + 8) * XPAD + kc];
            uint32_t ah2 = *(const uint32_t*)&Xhi[r0 * XPAD + kc + 8];
            uint32_t ah3 = *(const uint32_t*)&Xhi[(r0 + 8) * XPAD + kc + 8];
            uint32_t al0 = *(const uint32_t*)&Xlo[r0 * XPAD + kc];
            uint32_t al1 = *(const uint32_t*)&Xlo[(r0 + 8) * XPAD + kc];
            uint32_t al2 = *(const uint32_t*)&Xlo[r0 * XPAD + kc + 8];
            uint32_t al3 = *(const uint32_t*)&Xlo[(r0 + 8) * XPAD + kc + 8];
            #pragma unroll
            for (int nt = 0; nt < 8; nt++) {
                mma_bf16(acc[mt][nt], ah0, ah1, ah2, ah3, bh0[nt], bh1[nt]);
                mma_bf16(acc[mt][nt], ah0, ah1, ah2, ah3, bl0[nt], bl1[nt]);
                mma_bf16(acc[mt][nt], al0, al1, al2, al3, bh0[nt], bh1[nt]);
            }
        }
    }

    #pragma unroll
    for (int mt = 0; mt < 2; mt++) {
        int rl0 = mrow0 + mt * 16 + lr;
        int gr0 = row0 + rl0, gr1 = gr0 + 8;
        float ps0 = 0.f, ps1 = 0.f, pd0 = 0.f, pd1 = 0.f;
        #pragma unroll
        for (int nt = 0; nt < 8; nt++) {
            int c = ncol0 + nt * 8 + lq * 2;
            float s0 = avs[c], s1 = avs[c + 1];
            float d0 = avd[c], d1 = avd[c + 1];
            float* a = acc[mt][nt];
            ps0 += a[0] * s0 + a[1] * s1;
            pd0 += a[0] * d0 + a[1] * d1;
            ps1 += a[2] * s0 + a[3] * s1;
            pd1 += a[2] * d0 + a[3] * d1;
            if (gr0 < N_NODES)
                *(__half2*)&g_hh[(size_t)gr0 * D + c] = __floats2half2_rn(a[0], a[1]);
            if (gr1 < N_NODES)
                *(__half2*)&g_hh[(size_t)gr1 * D + c] = __floats2half2_rn(a[2], a[3]);
        }
        #pragma unroll
        for (int off = 1; off < 4; off <<= 1) {
            ps0 += __shfl_xor_sync(0xffffffffu, ps0, off);
            ps1 += __shfl_xor_sync(0xffffffffu, ps1, off);
            pd0 += __shfl_xor_sync(0xffffffffu, pd0, off);
            pd1 += __shfl_xor_sync(0xffffffffu, pd1, off);
        }
        if (lq == 0) {
            int half = warp & 1;
            as_s[rl0 * 2 + half] = ps0;       as_s[(rl0 + 8) * 2 + half] = ps1;
            ad_s[rl0 * 2 + half] = pd0;       ad_s[(rl0 + 8) * 2 + half] = pd1;
        }
    }
    __syncthreads();
    if (tid < 128) {
        int gr = row0 + tid;
        if (gr < N_NODES) {
            g_as[gr] = as_s[tid * 2] + as_s[tid * 2 + 1];
            g_ad[gr] = ad_s[tid * 2] + ad_s[tid * 2 + 1];
        }
    }
}

// ---------------- warp-per-node 2-pass softmax-aggregate (max-free, exact) --------
// mode 0: layer 1 -> relu, write g_o (fp32).
// mode 1: layer 2 -> block partial, scaled by 1/N, atomicAdd into out.
__global__ void __launch_bounds__(256) k_node_agg(int mode, const float* __restrict__ b,
                                                  float* __restrict__ out)
{
    __shared__ float sb[8 * 128];
    int node = (blockIdx.x * blockDim.x + threadIdx.x) >> 5;
    int warp = threadIdx.x >> 5;
    int lane = threadIdx.x & 31;

    int beg = g_rp[node];
    int end = g_rp[node + 1];
    float ad = g_ad[node];

    // pass A: unnormalized weights -> g_ew, accumulate denominator
    float wsum = 0.f;
    for (int j = beg + lane; j < end; j += 32) {
        float e = g_as[g_col[j]] + ad;
        e = fmaxf(e, 0.f) + 0.2f * fminf(e, 0.f);
        float w = __expf(e);
        g_ew[j] = w;
        wsum += w;
    }
    #pragma unroll
    for (int off = 16; off; off >>= 1)
        wsum += __shfl_xor_sync(0xffffffffu, wsum, off);
    float inv = 1.f / wsum;
    __syncwarp();

    // pass B: feature accumulate (lane owns 4 columns, fp16 gather = 8B/lane)
    float4 acc = make_float4(0.f, 0.f, 0.f, 0.f);
    for (int j = beg; j < end; j++) {
        int   s = g_col[j];     // warp-uniform broadcast
        float w = g_ew[j];      // warp-uniform broadcast
        uint2 raw = *(const uint2*)&g_hh[(size_t)s * D + lane * 4];
        float2 f01 = __half22float2(*(__half2*)&raw.x);
        float2 f23 = __half22float2(*(__half2*)&raw.y);
        acc.x = fmaf(w, f01.x, acc.x);
        acc.y = fmaf(w, f01.y, acc.y);
        acc.z = fmaf(w, f23.x, acc.z);
        acc.w = fmaf(w, f23.y, acc.w);
    }

    const float4 b4 = *(const float4*)&b[lane * 4];
    acc.x = fmaf(acc.x, inv, b4.x);
    acc.y = fmaf(acc.y, inv, b4.y);
    acc.z = fmaf(acc.z, inv, b4.z);
    acc.w = fmaf(acc.w, inv, b4.w);

    if (mode == 0) {
        acc.x = fmaxf(acc.x, 0.f); acc.y = fmaxf(acc.y, 0.f);
        acc.z = fmaxf(acc.z, 0.f); acc.w = fmaxf(acc.w, 0.f);
        *(float4*)&g_o[(size_t)node * D + lane * 4] = acc;
    } else {
        // layer 2: block partial sum, scaled by 1/N, accumulated into d_out
        *(float4*)&sb[warp * 128 + lane * 4] = acc;
        __syncthreads();
        if (threadIdx.x < 128) {
            float s = 0.f;
            #pragma unroll
            for (int w = 0; w < 8; w++) s += sb[w * 128 + threadIdx.x];
            atomicAdd(&out[threadIdx.x], s * (1.0f / N_NODES));
        }
    }
}

// ---------------- zero d_out (poisoned 0xAA by harness) ---------------------------
__global__ void k_zero_out(float* __restrict__ out) {
    if (threadIdx.x < 128) out[threadIdx.x] = 0.f;
}

// ---------------- driver: fork CSR build onto a side stream, join before agg1 -----
extern "C" void kernel_launch(void* const* d_in, const int* in_sizes, int n_in,
                              void* d_out, int out_size)
{
    const float* x   = (const float*)d_in[0];
    const int*   ei  = (const int*)d_in[1];      // int32: [src x E | dst x E]
    const float* W1  = (const float*)d_in[2];
    const float* as1 = (const float*)d_in[3];
    const float* ad1 = (const float*)d_in[4];
    const float* b1  = (const float*)d_in[5];
    const float* W2  = (const float*)d_in[6];
    const float* as2 = (const float*)d_in[7];
    const float* ad2 = (const float*)d_in[8];
    const float* b2  = (const float*)d_in[9];
    float* out = (float*)d_out;

    // one-time host-object setup (first call is the uncaptured correctness run;
    // no device memory is allocated here)
    static cudaStream_t s2 = nullptr;
    static cudaEvent_t ev_fork = nullptr, ev_csr = nullptr;
    if (s2 == nullptr) {
        cudaStreamCreateWithFlags(&s2, cudaStreamNonBlocking);
        cudaEventCreateWithFlags(&ev_fork, cudaEventDisableTiming);
        cudaEventCreateWithFlags(&ev_csr,  cudaEventDisableTiming);
        cudaFuncSetAttribute(k_gemm, cudaFuncAttributeMaxDynamicSharedMemorySize, SM_TOT);
    }

    // fork: side stream zeroes d_out + builds CSR while main stream does
    // wsplit + layer-1 GEMM
    cudaEventRecord(ev_fork, 0);
    cudaStreamWaitEvent(s2, ev_fork, 0);

    k_zero_out <<<1, 128, 0, s2>>>(out);
    k_deg_count<<<(N_EDGES + 255) / 256, 256, 0, s2>>>(ei);
    k_scan1    <<<NB, SCAN_B, 0, s2>>>();
    k_scan23   <<<(N_NODES + 255) / 256, 256, 0, s2>>>();
    k_scatter  <<<(E_TOT + 255) / 256, 256, 0, s2>>>(ei);
    cudaEventRecord(ev_csr, s2);

    k_wsplit<<<(2 * D * D + 255) / 256, 256>>>(W1, W2);
    k_gemm  <<<N_TILES, 256, SM_TOT>>>(x, 1, 0, as1, ad1);

    // join: aggregation needs the CSR, layer-1 H/alphas, and zeroed d_out
    cudaStreamWaitEvent(0, ev_csr, 0);

    // layer 1 aggregate -> g_o (relu, fp32)
    k_node_agg<<<AGG_BLKS, 256>>>(0, b1, out);

    // layer 2: g_o -> g_hh -> scaled partials atomically accumulated into d_out
    k_gemm    <<<N_TILES, 256, SM_TOT>>>(nullptr, 0, 1, as2, ad2);
    k_node_agg<<<AGG_BLKS, 256>>>(1, b2, out);
}